// round 9
// baseline (speedup 1.0000x reference)
#include <cuda_runtime.h>
#include <cuda_bf16.h>
#include <cstdint>
#include <algorithm>

// ---------------------------------------------------------------------------
// UniformNeighborSampler:
//   out[r, j] = (float) adj[g_id, ids[r], sel[j]],  g_id=1, ins=1 (adj_ins)
//   sel = jax.random.permutation(jax.random.key(42), 128)[:32]
//     (partitionable threefry, verified exact since R4)
//
// R9: full-row loads via ld.global.nc.L2::evict_last.v8.b32 (the encoding
// ptxas accepts for evict_last). 16 lanes x 32B = one 512B row per half-warp,
// 2 rows per instruction: fully sequential DRAM granules + native L2
// pinning so graph replays hit L2. Rows staged in warp-private smem, sampled
// columns picked via LDS, coalesced 128B stores.
// ---------------------------------------------------------------------------

namespace {

constexpr int N_GRAPHS      = 4;
constexpr int DEGREES       = 128;
constexpr int SAMPLES       = 32;
constexpr int G_ID          = 1;
constexpr int ROWS_PER_WARP = 8;
constexpr int WARPS_PER_BLK = 8;

struct Sel32 { int s[SAMPLES]; };

static inline uint32_t rotl32(uint32_t x, int d) {
    return (x << d) | (x >> (32 - d));
}

static void threefry2x32(uint32_t k0, uint32_t k1,
                         uint32_t c0, uint32_t c1,
                         uint32_t* o0, uint32_t* o1) {
    uint32_t ks[3] = {k0, k1, k0 ^ k1 ^ 0x1BD11BDAu};
    uint32_t x0 = c0 + ks[0];
    uint32_t x1 = c1 + ks[1];
    static const int rot[2][4] = {{13, 15, 26, 6}, {17, 29, 16, 24}};
    for (int i = 0; i < 5; i++) {
        const int* r = rot[i & 1];
        for (int j = 0; j < 4; j++) {
            x0 += x1;
            x1 = rotl32(x1, r[j]);
            x1 ^= x0;
        }
        x0 += ks[(i + 1) % 3];
        x1 += ks[(i + 2) % 3] + (uint32_t)(i + 1);
    }
    *o0 = x0;
    *o1 = x1;
}

static void compute_sel(Sel32* sel) {
    const uint32_t k0 = 0u, k1 = 42u;          // jax.random.key(42)

    uint32_t sk0, sk1;                          // partitionable split
    threefry2x32(k0, k1, 0u, 1u, &sk0, &sk1);

    uint32_t bits[DEGREES];                     // counter-mode bits, xor-fold
    for (int i = 0; i < DEGREES; i++) {
        uint32_t y0, y1;
        threefry2x32(sk0, sk1, 0u, (uint32_t)i, &y0, &y1);
        bits[i] = y0 ^ y1;
    }

    uint64_t kv[DEGREES];
    for (int i = 0; i < DEGREES; i++)
        kv[i] = ((uint64_t)bits[i] << 32) | (uint32_t)i;
    std::sort(kv, kv + DEGREES);

    for (int j = 0; j < SAMPLES; j++)
        sel->s[j] = (int)(kv[j] & 0xFFFFFFFFu);
}

} // namespace

// 256-bit row-chunk load with native L2 evict_last (pins row in L2).
__device__ __forceinline__ void ldg256_evict_last(const int* p, int* v) {
    asm volatile(
        "ld.global.nc.L2::evict_last.v8.b32 {%0,%1,%2,%3,%4,%5,%6,%7}, [%8];"
        : "=r"(v[0]), "=r"(v[1]), "=r"(v[2]), "=r"(v[3]),
          "=r"(v[4]), "=r"(v[5]), "=r"(v[6]), "=r"(v[7])
        : "l"(p));
}

__global__ __launch_bounds__(WARPS_PER_BLK * 32)
void uniform_neighbor_sampler_kernel(const int* __restrict__ adj_g,
                                     const int* __restrict__ ids,
                                     float* __restrict__ out,
                                     int batch, Sel32 sel)
{
    // warp-private staging: 8 rows x 512B = 4KB/warp -> 32KB/block
    __shared__ int srow[WARPS_PER_BLK][ROWS_PER_WARP][DEGREES];

    const int wib  = threadIdx.x >> 5;
    const int lane = threadIdx.x & 31;
    const int warp = blockIdx.x * WARPS_PER_BLK + wib;

    const long long row0 = (long long)warp * ROWS_PER_WARP;
    if (row0 >= batch) return;

    // Coalesced ids load: lanes 0..7 fetch the 8 row ids.
    int myid = 0;
    if (lane < ROWS_PER_WARP && row0 + lane < batch)
        myid = __ldg(&ids[row0 + lane]);

    // Full-row loads, 2 rows per instruction:
    //   pair = lane>>4 selects row (2*it + pair), sub = lane&15 selects the
    //   32B chunk. 4 front-batched v8.b32 loads cover all 8 rows (MLP=4x512B).
    const int pair = lane >> 4;        // 0 or 1
    const int sub  = lane & 15;        // 32B chunk index within row
    int v[4][8];
#pragma unroll
    for (int it = 0; it < 4; it++) {
        int r  = 2 * it + pair;
        int id = __shfl_sync(0xffffffffu, myid, r);
        ldg256_evict_last(adj_g + (long long)id * DEGREES + sub * 8, v[it]);
    }

    // Stage to smem: each lane writes its 32B chunk (2x st.shared.v4).
#pragma unroll
    for (int it = 0; it < 4; it++) {
        int r = 2 * it + pair;
        int4* dst = reinterpret_cast<int4*>(&srow[wib][r][sub * 8]);
        dst[0] = make_int4(v[it][0], v[it][1], v[it][2], v[it][3]);
        dst[1] = make_int4(v[it][4], v[it][5], v[it][6], v[it][7]);
    }

    __syncwarp();

    // Pick sampled columns; coalesced 128B store per row.
    const int col = sel.s[lane];
#pragma unroll
    for (int r = 0; r < ROWS_PER_WARP; r++) {
        long long row = row0 + r;
        if (row < batch)
            out[row * SAMPLES + lane] = (float)srow[wib][r][col];
    }
}

extern "C" void kernel_launch(void* const* d_in, const int* in_sizes, int n_in,
                              void* d_out, int out_size)
{
    // Locate inputs by SIZE (layout-order independent).
    int adj_idx0 = -1, adj_idx1 = -1, ids_idx = -1;
    for (int i = 0; i < n_in; i++) {
        long long sz = in_sizes[i];
        if (sz > 1000000) {
            if (adj_idx0 < 0) adj_idx0 = i;
            else if (adj_idx1 < 0) adj_idx1 = i;
        } else if (sz > 1) {
            ids_idx = i;
        }
    }
    if (adj_idx0 < 0) adj_idx0 = 0;
    if (adj_idx1 < 0) adj_idx1 = 1;
    if (ids_idx  < 0) ids_idx  = 3;

    const int* adj_ins = (const int*)d_in[adj_idx0];   // ins=1 -> active table
    const int* ids     = (const int*)d_in[ids_idx];

    const int num_nodes = in_sizes[adj_idx0] / (N_GRAPHS * DEGREES);
    const int batch     = in_sizes[ids_idx];           // 50000 rows

    const int* adj_g = adj_ins + (long long)G_ID * num_nodes * DEGREES;

    Sel32 sel;
    compute_sel(&sel);

    const int threads = WARPS_PER_BLK * 32;            // 256
    const int rows_per_block = WARPS_PER_BLK * ROWS_PER_WARP;  // 64
    const int blocks = (batch + rows_per_block - 1) / rows_per_block;  // 782

    uniform_neighbor_sampler_kernel<<<blocks, threads>>>(
        adj_g, ids, (float*)d_out, batch, sel);
}